// round 16
// baseline (speedup 1.0000x reference)
#include <cuda_runtime.h>
#include <cuda_fp16.h>
#include <cstdint>

#define F_IN     256
#define F_OUT    128
#define MAX_N    100352            // 98 * 1024, covers 100000
#define MAX_E    1600000
#define SCAN_BLK 1024

// Static scratch — __device__ globals (no allocation allowed).
__device__ __half g_h16[(size_t)100000 * F_OUT];  // h = x @ W, fp16 (25.6 MB)
__device__ __half g_Bh16[F_IN * F_OUT];           // W^T fp16, [n][k]
__device__ int   g_cnt[MAX_N];                    // zeroed by scanA each run
__device__ int   g_scan[MAX_N];
__device__ int   g_bsum[256];                     // RAW block sums (no scanB)
__device__ int   g_off[MAX_N + 1];
__device__ int   g_cur[MAX_N];
__device__ int2  g_edge[MAX_E];                   // (src, val_bits) CSR order

// ---------------------------------------------------------------------------
// CSR build: count(x4) -> scanA(+self-zero) -> scanC(inline block prefix)
//            -> fill(x4).   4 launches total.
// g_cnt is zero on entry: module-load zeros on first run; scanA re-zeros
// after reading on every run (count re-increments from 0 -> deterministic).
// ---------------------------------------------------------------------------
__global__ void count_kernel(const int* __restrict__ edge_dst, int E) {
    int i = (blockIdx.x * blockDim.x + threadIdx.x) * 4;
    if (i + 3 < E) {
        int4 d = *(const int4*)(edge_dst + i);
        atomicAdd(&g_cnt[d.x], 1);
        atomicAdd(&g_cnt[d.y], 1);
        atomicAdd(&g_cnt[d.z], 1);
        atomicAdd(&g_cnt[d.w], 1);
    } else {
        for (int k = i; k < E; k++) atomicAdd(&g_cnt[edge_dst[k]], 1);
    }
}

__global__ __launch_bounds__(SCAN_BLK)
void scanA_kernel() {
    __shared__ int s[SCAN_BLK];
    int t = threadIdx.x;
    int i = blockIdx.x * SCAN_BLK + t;
    int v = g_cnt[i];
    g_cnt[i] = 0;                               // restore zero for next run
    s[t] = v;
    __syncthreads();
    #pragma unroll
    for (int off = 1; off < SCAN_BLK; off <<= 1) {
        int tmp = (t >= off) ? s[t - off] : 0;
        __syncthreads();
        s[t] += tmp;
        __syncthreads();
    }
    g_scan[i] = s[t] - v;                       // exclusive within block
    if (t == SCAN_BLK - 1) g_bsum[blockIdx.x] = s[t];   // RAW block total
}

// scanC: each 256-thread block lies fully inside one 1024-chunk (256 | 1024),
// so one warp-reduce over g_bsum[0..chunk) gives the block-wide prefix.
__global__ __launch_bounds__(256)
void scanC_kernel(int N, int E) {
    __shared__ int pfx;
    const int chunk = (blockIdx.x * 256) / SCAN_BLK;
    if (threadIdx.x < 32) {
        int sum = 0;
        for (int j = threadIdx.x; j < chunk; j += 32) sum += g_bsum[j];
        #pragma unroll
        for (int o = 16; o; o >>= 1) sum += __shfl_xor_sync(0xFFFFFFFFu, sum, o);
        if (threadIdx.x == 0) pfx = sum;
    }
    __syncthreads();
    int i = blockIdx.x * 256 + threadIdx.x;
    if (i <= N) {
        int o = (i == N) ? E : (g_scan[i] + pfx);
        g_off[i] = o;
        if (i < N) g_cur[i] = o;
    }
}

__global__ void fill_kernel(const int* __restrict__ edge_dst,
                            const int* __restrict__ edge_src,
                            const float* __restrict__ edge_vals, int E) {
    int i = (blockIdx.x * blockDim.x + threadIdx.x) * 4;
    if (i + 3 < E) {
        int4   d = *(const int4*)(edge_dst + i);
        int4   s = *(const int4*)(edge_src + i);
        float4 v = *(const float4*)(edge_vals + i);
        int p0 = atomicAdd(&g_cur[d.x], 1);
        int p1 = atomicAdd(&g_cur[d.y], 1);
        int p2 = atomicAdd(&g_cur[d.z], 1);
        int p3 = atomicAdd(&g_cur[d.w], 1);
        g_edge[p0] = make_int2(s.x, __float_as_int(v.x));
        g_edge[p1] = make_int2(s.y, __float_as_int(v.y));
        g_edge[p2] = make_int2(s.z, __float_as_int(v.z));
        g_edge[p3] = make_int2(s.w, __float_as_int(v.w));
    } else {
        for (int k = i; k < E; k++) {
            int p = atomicAdd(&g_cur[edge_dst[k]], 1);
            g_edge[p] = make_int2(edge_src[k], __float_as_int(edge_vals[k]));
        }
    }
}

// ---------------------------------------------------------------------------
// Kernel 2a: W transpose to fp16:  Bh[n][k] = fp16(w[k][n])
// ---------------------------------------------------------------------------
__global__ void wsplit_kernel(const float* __restrict__ w,
                              __half* __restrict__ bh) {
    int k = blockIdx.x;        // 0..255
    int n = threadIdx.x;       // 0..127
    bh[n * F_IN + k] = __float2half_rn(w[k * F_OUT + n]);
}

// ---------------------------------------------------------------------------
// Kernel 2b: mma.sync fp16 GEMM (single pass) — unchanged golden version.
// ---------------------------------------------------------------------------
#define KC       32
#define NCHUNK   (F_IN / KC)       // 8
#define ASU      20                // u32 per SMEM row (16 data + 4 pad)
#define SM_A     0
#define SM_BH    (128 * ASU)
#define GEMM_SMEM_BYTES (2 * 128 * ASU * 4)   // 20480

__device__ __forceinline__ uint32_t pack_h2(float a, float b) {
    __half2 t = __floats2half2_rn(a, b);   // .x = a (low half)
    return *(uint32_t*)&t;
}

__device__ __forceinline__ void mma_f16(float* d, const uint32_t* a,
                                        const uint32_t* b) {
    asm volatile(
        "mma.sync.aligned.m16n8k16.row.col.f32.f16.f16.f32 "
        "{%0, %1, %2, %3}, {%4, %5, %6, %7}, {%8, %9}, {%0, %1, %2, %3};"
        : "+f"(d[0]), "+f"(d[1]), "+f"(d[2]), "+f"(d[3])
        : "r"(a[0]), "r"(a[1]), "r"(a[2]), "r"(a[3]), "r"(b[0]), "r"(b[1]));
}

__global__ __launch_bounds__(256, 2)
void gemm_mma_kernel(const float* __restrict__ x,
                     const __half* __restrict__ bh_g,
                     __half* __restrict__ h16, int M) {
    extern __shared__ uint32_t smu[];
    const int tid  = threadIdx.x;
    const int wid  = tid >> 5;
    const int lane = tid & 31;
    const int g = lane >> 2;
    const int t = lane & 3;
    const int wm = wid & 3;
    const int wn = wid >> 2;
    const int block_row = blockIdx.x * 128;

    const uint32_t* bhu = (const uint32_t*)bh_g;   // [n][128] u32 rows
    uint32_t* hu = (uint32_t*)h16;                 // h as u32 (half2) words

    float acc[2][8][4];
    #pragma unroll
    for (int i = 0; i < 2; i++)
        #pragma unroll
        for (int j = 0; j < 8; j++)
            #pragma unroll
            for (int q = 0; q < 4; q++) acc[i][j][q] = 0.0f;

    for (int c = 0; c < NCHUNK; c++) {
        if (c > 0) __syncthreads();
        // ---- A: 128 rows x 32 k; fp32 -> fp16, packed u32 pairs ----
        #pragma unroll
        for (int i = 0; i < 4; i++) {
            int fidx = i * 256 + tid;          // 1024 float4 slots
            int row = fidx >> 3, c4 = fidx & 7;
            int grow = block_row + row;
            float4 v = make_float4(0.f, 0.f, 0.f, 0.f);
            if (grow < M)
                v = *(const float4*)(x + (size_t)grow * F_IN + c * KC + c4 * 4);
            uint32_t base = row * ASU + c4 * 2;
            *(uint2*)&smu[SM_A + base] =
                make_uint2(pack_h2(v.x, v.y), pack_h2(v.z, v.w));
        }
        // ---- B: 128 n-rows x 32 k (fp16 in gmem) ----
        {
            int fidx = tid;                    // 256 uint4 slots
            int row = fidx >> 1, q = fidx & 1;
            const size_t go = (size_t)row * (F_IN / 2) + c * (KC / 2) + q * 8;
            uint4 vh0 = *(const uint4*)(bhu + go);
            uint4 vh1 = *(const uint4*)(bhu + go + 4);
            uint32_t base = row * ASU + q * 8;
            *(uint4*)&smu[SM_BH + base] = vh0;
            *(uint4*)&smu[SM_BH + base + 4] = vh1;
        }
        __syncthreads();

        #pragma unroll
        for (int kp = 0; kp < KC / 2; kp += 8) {   // two k16 steps
            uint32_t a[2][4];
            #pragma unroll
            for (int mt = 0; mt < 2; mt++) {
                int r0 = (wm * 32 + mt * 16 + g) * ASU + kp + t;
                int r8 = (wm * 32 + mt * 16 + g + 8) * ASU + kp + t;
                a[mt][0] = smu[SM_A + r0];
                a[mt][1] = smu[SM_A + r8];
                a[mt][2] = smu[SM_A + r0 + 4];
                a[mt][3] = smu[SM_A + r8 + 4];
            }
            #pragma unroll
            for (int nt = 0; nt < 8; nt++) {
                int nrow = (wn * 64 + nt * 8 + g) * ASU + kp + t;
                uint32_t bh[2];
                bh[0] = smu[SM_BH + nrow];
                bh[1] = smu[SM_BH + nrow + 4];
                #pragma unroll
                for (int mt = 0; mt < 2; mt++)
                    mma_f16(acc[mt][nt], a[mt], bh);
            }
        }
    }

    // ---- writeback h as fp16 (one u32 = half2 per fragment pair) ----
    #pragma unroll
    for (int mt = 0; mt < 2; mt++) {
        int row0 = block_row + wm * 32 + mt * 16 + g;
        int row8 = row0 + 8;
        #pragma unroll
        for (int nt = 0; nt < 8; nt++) {
            int col = wn * 64 + nt * 8 + 2 * t;       // even
            if (row0 < M)
                hu[((size_t)row0 * F_OUT + col) >> 1] =
                    pack_h2(acc[mt][nt][0], acc[mt][nt][1]);
            if (row8 < M)
                hu[((size_t)row8 * F_OUT + col) >> 1] =
                    pack_h2(acc[mt][nt][2], acc[mt][nt][3]);
        }
    }
}

// ---------------------------------------------------------------------------
// Kernel 3: CSR aggregation — GOLDEN R15 version (untouched).
// ---------------------------------------------------------------------------
__global__ __launch_bounds__(256)
void aggregate_kernel(const __half* __restrict__ h16,
                      const float* __restrict__ bias,
                      float* __restrict__ out, int N) {
    const int warp = (blockIdx.x * blockDim.x + threadIdx.x) >> 5;
    const int lane = threadIdx.x & 31;
    if (warp >= N) return;

    const int s0 = g_off[warp];
    const int s1 = g_off[warp + 1];
    float4 acc = ((const float4*)bias)[lane];

    for (int base = s0; base < s1; base += 32) {
        int s = 0; float v = 0.0f;
        if (base + lane < s1) {
            int2 e = g_edge[base + lane];
            s = e.x;
            v = __int_as_float(e.y);
        }
        const int cnt = min(32, s1 - base);
        #pragma unroll 4
        for (int j = 0; j < cnt; j++) {
            int   ss = __shfl_sync(0xFFFFFFFFu, s, j);
            float vv = __shfl_sync(0xFFFFFFFFu, v, j);
            uint2 raw = ((const uint2*)(h16 + (size_t)ss * F_OUT))[lane];
            float2 f0 = __half22float2(*(const __half2*)&raw.x);
            float2 f1 = __half22float2(*(const __half2*)&raw.y);
            acc.x += f0.x * vv; acc.y += f0.y * vv;
            acc.z += f1.x * vv; acc.w += f1.y * vv;
        }
    }
    ((float4*)(out + (size_t)warp * F_OUT))[lane] = acc;
}

// ---------------------------------------------------------------------------
// Launch.  Inputs: x[f32], edge_src[i32], edge_dst[i32], edge_vals[f32],
//                  kernel[f32], bias[f32]
// CSR build (4 launches) forked onto a side stream, overlapped with
// wsplit+GEMM; join before aggregate.
// ---------------------------------------------------------------------------
extern "C" void kernel_launch(void* const* d_in, const int* in_sizes, int n_in,
                              void* d_out, int out_size) {
    const float* x    = (const float*)d_in[0];
    const int*   esrc = (const int*)d_in[1];
    const int*   edst = (const int*)d_in[2];
    const float* eval = (const float*)d_in[3];
    const float* w    = (const float*)d_in[4];
    const float* bias = (const float*)d_in[5];
    float*       out  = (float*)d_out;

    const int M = in_sizes[0] / F_IN;     // 100000 nodes
    const int E = in_sizes[1];            // 1.6M edges
    const int n_pad  = ((M + SCAN_BLK - 1) / SCAN_BLK) * SCAN_BLK;
    const int n_sblk = n_pad / SCAN_BLK;  // 98
    (void)n_sblk;

    __half *h16, *bh;
    cudaGetSymbolAddress((void**)&h16, g_h16);
    cudaGetSymbolAddress((void**)&bh,  g_Bh16);

    static cudaStream_t s2 = nullptr;
    static cudaEvent_t ev_fork = nullptr, ev_join = nullptr;
    static int init_done = 0;
    if (!init_done) {
        cudaStreamCreateWithFlags(&s2, cudaStreamNonBlocking);
        cudaEventCreateWithFlags(&ev_fork, cudaEventDisableTiming);
        cudaEventCreateWithFlags(&ev_join, cudaEventDisableTiming);
        cudaFuncSetAttribute(gemm_mma_kernel,
                             cudaFuncAttributeMaxDynamicSharedMemorySize,
                             GEMM_SMEM_BYTES);
        init_done = 1;
    }

    // ---- fork: CSR build on s2 (4 launches) ----
    cudaEventRecord(ev_fork, 0);
    cudaStreamWaitEvent(s2, ev_fork, 0);
    count_kernel<<<(E / 4 + 255) / 256, 256, 0, s2>>>(edst, E);
    scanA_kernel<<<n_pad / SCAN_BLK, SCAN_BLK, 0, s2>>>();
    scanC_kernel<<<(M + 256) / 256, 256, 0, s2>>>(M, E);
    fill_kernel<<<(E / 4 + 255) / 256, 256, 0, s2>>>(edst, esrc, eval, E);
    cudaEventRecord(ev_join, s2);

    // ---- main stream: dense path ----
    wsplit_kernel<<<F_IN, F_OUT>>>(w, bh);
    {
        int blocks = (M + 127) / 128;
        gemm_mma_kernel<<<blocks, 256, GEMM_SMEM_BYTES>>>(x, bh, h16, M);
    }

    // ---- join, then aggregate ----
    cudaStreamWaitEvent(0, ev_join, 0);
    {
        int blocks = (M * 32 + 255) / 256;   // 12500
        aggregate_kernel<<<blocks, 256>>>(h16, bias, out, M);
    }
}